// round 3
// baseline (speedup 1.0000x reference)
#include <cuda_runtime.h>
#include <cuda_bf16.h>
#include <math.h>

#define B_    4
#define N_    4096
#define D_    1024
#define H_    16
#define DH_   64
#define M_    256
#define DFF_  4096
#define RTOT_ (B_*N_)     // 16384
#define BH_   (B_*H_)     // 64

#define NORM_   0.35355339059327373f   // 64^-0.25
#define DIAGF_  0.0625f                // 0.5 * 64^-0.5
#define RATIO_  0.0625f                // 256^-0.5
#define EPSK_   1e-4f
#define LNEPS_  1e-5f

// ---------------- scratch (static device globals; no allocation) ----------------
__device__ float g_Q[RTOT_ * D_];            // Q acts -> attn-ctx -> ffn out
__device__ float g_K[RTOT_ * D_];            // K acts -> attn (post-Wo)
__device__ float g_V[RTOT_ * D_];            // V acts -> x (post-LN1)
__device__ float g_phiQ[BH_ * N_ * M_];      // xp_q -> qp
__device__ float g_phiK[BH_ * N_ * M_];      // xp_k -> kp
__device__ float g_ctx[BH_ * M_ * DH_];
__device__ float g_ksum[BH_ * M_];
__device__ float g_bhmax[BH_];
__device__ float g_H[RTOT_ * DFF_];          // ffn hidden

// ---------------- big tiled SGEMM: C = A @ W^T + bias (opt ReLU) ----------------
// A: [rows x K] row-major, W: [Ncols x K] row-major, C: [rows x Ncols]
// BM=BN=128, BK=16, 256 threads, 8x8 microtile.
// grid = (Ncols/128, rows/128). Requires rows%128==0, Ncols%128==0, K%16==0.
template<bool RELU>
__global__ __launch_bounds__(256)
void sgemm_bias_kernel(const float* __restrict__ A,
                       const float* __restrict__ W,
                       const float* __restrict__ bias,
                       float* __restrict__ C,
                       int K, int Ncols) {
    __shared__ float As[16][132];
    __shared__ float Ws[16][132];
    const int row0 = blockIdx.y * 128;
    const int col0 = blockIdx.x * 128;
    const int tid = threadIdx.x;
    const int lr  = tid >> 2;          // 0..63 (row within half-tile)
    const int lk4 = (tid & 3) * 4;     // 0,4,8,12
    const int tx = tid & 15;           // 0..15 -> col microtile
    const int ty = tid >> 4;           // 0..15 -> row microtile

    float acc[8][8];
    #pragma unroll
    for (int i = 0; i < 8; i++)
        #pragma unroll
        for (int j = 0; j < 8; j++) acc[i][j] = 0.f;

    for (int k0 = 0; k0 < K; k0 += 16) {
        #pragma unroll
        for (int r = 0; r < 2; r++) {
            const int m = lr + r * 64;
            float4 av = *(const float4*)&A[(size_t)(row0 + m) * K + k0 + lk4];
            As[lk4 + 0][m] = av.x; As[lk4 + 1][m] = av.y;
            As[lk4 + 2][m] = av.z; As[lk4 + 3][m] = av.w;
            float4 wv = *(const float4*)&W[(size_t)(col0 + m) * K + k0 + lk4];
            Ws[lk4 + 0][m] = wv.x; Ws[lk4 + 1][m] = wv.y;
            Ws[lk4 + 2][m] = wv.z; Ws[lk4 + 3][m] = wv.w;
        }
        __syncthreads();
        #pragma unroll
        for (int k = 0; k < 16; k++) {
            float a[8], b[8];
            *(float4*)&a[0] = *(const float4*)&As[k][ty * 8];
            *(float4*)&a[4] = *(const float4*)&As[k][ty * 8 + 4];
            *(float4*)&b[0] = *(const float4*)&Ws[k][tx * 8];
            *(float4*)&b[4] = *(const float4*)&Ws[k][tx * 8 + 4];
            #pragma unroll
            for (int i = 0; i < 8; i++)
                #pragma unroll
                for (int j = 0; j < 8; j++)
                    acc[i][j] += a[i] * b[j];
        }
        __syncthreads();
    }

    #pragma unroll
    for (int i = 0; i < 8; i++) {
        const int r = row0 + ty * 8 + i;
        #pragma unroll
        for (int j = 0; j < 8; j += 4) {
            const int c = col0 + tx * 8 + j;
            float4 v;
            v.x = acc[i][j + 0] + bias[c + 0];
            v.y = acc[i][j + 1] + bias[c + 1];
            v.z = acc[i][j + 2] + bias[c + 2];
            v.w = acc[i][j + 3] + bias[c + 3];
            if (RELU) {
                v.x = fmaxf(v.x, 0.f); v.y = fmaxf(v.y, 0.f);
                v.z = fmaxf(v.z, 0.f); v.w = fmaxf(v.w, 0.f);
            }
            *(float4*)&C[(size_t)r * Ncols + c] = v;
        }
    }
}

// ---------------- phi GEMM: xp[bh][n][m] = NORM * sum_d Act[b,n,h*64+d]*proj[m][d] ----------------
// grid = (M/64=4, N/64=64, BH=64), block = 256
__global__ void phi_gemm_kernel(const float* __restrict__ Act,
                                const float* __restrict__ proj,
                                float* __restrict__ Xp) {
    const int z = blockIdx.z;            // bh
    const int b = z >> 4, h = z & 15;
    const float* A = Act + (size_t)b * N_ * D_ + h * DH_;   // rows stride D_
    float* C = Xp + (size_t)z * N_ * M_;

    __shared__ float As[16][65];
    __shared__ float Ws[16][65];
    const int row0 = blockIdx.y * 64;
    const int col0 = blockIdx.x * 64;
    const int tid = threadIdx.x;
    const int lk = tid & 15, lm = tid >> 4;
    const int tx = tid & 15, ty = tid >> 4;
    float acc[4][4];
    #pragma unroll
    for (int i = 0; i < 4; i++)
        #pragma unroll
        for (int j = 0; j < 4; j++) acc[i][j] = 0.f;

    for (int k0 = 0; k0 < DH_; k0 += 16) {
        #pragma unroll
        for (int i = 0; i < 4; i++) {
            int m = lm + i * 16;
            As[lk][m] = A[(size_t)(row0 + m) * D_ + k0 + lk];
            Ws[lk][m] = proj[(size_t)(col0 + m) * DH_ + k0 + lk];
        }
        __syncthreads();
        #pragma unroll
        for (int k = 0; k < 16; k++) {
            float a[4], bb[4];
            #pragma unroll
            for (int i = 0; i < 4; i++) a[i] = As[k][ty * 4 + i];
            #pragma unroll
            for (int j = 0; j < 4; j++) bb[j] = Ws[k][tx * 4 + j];
            #pragma unroll
            for (int i = 0; i < 4; i++)
                #pragma unroll
                for (int j = 0; j < 4; j++)
                    acc[i][j] += a[i] * bb[j];
        }
        __syncthreads();
    }
    #pragma unroll
    for (int i = 0; i < 4; i++) {
        int r = row0 + ty * 4 + i;
        #pragma unroll
        for (int j = 0; j < 4; j++)
            C[(size_t)r * M_ + col0 + tx * 4 + j] = acc[i][j] * NORM_;
    }
}

// ---------------- per-(b,h) global max over raw xp ----------------
__global__ void bhmax_kernel(const float* __restrict__ Xp, float* __restrict__ outMax) {
    const int bh = blockIdx.x;
    const float4* p = (const float4*)(Xp + (size_t)bh * N_ * M_);
    const int tot = N_ * M_ / 4;
    float m = -3.4e38f;
    for (int i = threadIdx.x; i < tot; i += 256) {
        float4 v = p[i];
        m = fmaxf(m, fmaxf(fmaxf(v.x, v.y), fmaxf(v.z, v.w)));
    }
    __shared__ float red[256];
    red[threadIdx.x] = m;
    __syncthreads();
    for (int o = 128; o >= 1; o >>= 1) {
        if (threadIdx.x < o) red[threadIdx.x] = fmaxf(red[threadIdx.x], red[threadIdx.x + o]);
        __syncthreads();
    }
    if (threadIdx.x == 0) outMax[bh] = red[0];
}

// ---------------- finalize: xp -> RATIO*(exp(xp - diag - stab)+eps) ----------------
// grid = BH_*N_ blocks, block = 256 (one thread per m)
template<bool ISQ>
__global__ void phi_finalize_kernel(float* __restrict__ Xp,
                                    const float* __restrict__ Act,
                                    const float* __restrict__ bhmaxArr) {
    const int row = blockIdx.x;          // bh*N + n
    const int bh = row >> 12;
    const int n  = row & (N_ - 1);
    const int b = bh >> 4, h = bh & 15;
    const int t = threadIdx.x;
    __shared__ float red[256];

    const float* x = Act + ((size_t)b * N_ + n) * D_ + h * DH_;
    float ss = 0.f;
    if (t < 64) { float v = x[t]; ss = v * v; }
    red[t] = ss;
    __syncthreads();
    for (int o = 32; o >= 1; o >>= 1) {
        if (t < o) red[t] += red[t + o];
        __syncthreads();
    }
    const float diag = red[0] * DIAGF_;
    __syncthreads();

    float xp = Xp[(size_t)row * M_ + t];
    float stab;
    if (ISQ) {
        red[t] = xp;
        __syncthreads();
        for (int o = 128; o >= 1; o >>= 1) {
            if (t < o) red[t] = fmaxf(red[t], red[t + o]);
            __syncthreads();
        }
        stab = red[0];
    } else {
        stab = bhmaxArr[bh];
    }
    Xp[(size_t)row * M_ + t] = RATIO_ * (__expf(xp - diag - stab) + EPSK_);
}

// ---------------- k_sum[bh][m] = sum_n kp[bh][n][m] ----------------
__global__ void ksum_kernel(const float* __restrict__ Kp, float* __restrict__ ks) {
    const int bh = blockIdx.x;
    const float* p = Kp + (size_t)bh * N_ * M_ + threadIdx.x;
    float s = 0.f;
    #pragma unroll 8
    for (int n = 0; n < N_; n++) s += p[(size_t)n * M_];
    ks[bh * M_ + threadIdx.x] = s;
}

__global__ void zero_kernel(float* __restrict__ p, int n) {
    int i = blockIdx.x * 256 + threadIdx.x;
    if (i < n) p[i] = 0.f;
}

// ---------------- ctx[bh][m][d] = sum_n kp[bh][n][m] * v[b,n,h*64+d] ----------------
// grid = (8 splits, BH_), block = (64, 4). float atomics into zeroed ctx.
__global__ void ctx_kernel(const float* __restrict__ Kp,
                           const float* __restrict__ V,
                           float* __restrict__ ctx) {
    const int bh = blockIdx.y;
    const int b = bh >> 4, h = bh & 15;
    const int d = threadIdx.x;
    const int tg = threadIdx.y;          // 0..3 -> m block of 64
    const int n0 = blockIdx.x * (N_ / 8);

    float acc[64];
    #pragma unroll
    for (int i = 0; i < 64; i++) acc[i] = 0.f;

    const float* kp = Kp + (size_t)bh * N_ * M_ + tg * 64;
    const float* v  = V + (size_t)b * N_ * D_ + h * DH_ + d;

    for (int n = n0; n < n0 + N_ / 8; n++) {
        float vv = v[(size_t)n * D_];
        const float* kr = kp + (size_t)n * M_;
        #pragma unroll
        for (int i = 0; i < 64; i++) acc[i] += kr[i] * vv;
    }
    float* cb = ctx + (size_t)bh * M_ * DH_ + (tg * 64) * DH_ + d;
    #pragma unroll
    for (int i = 0; i < 64; i++) atomicAdd(cb + i * DH_, acc[i]);
}

// ---------------- out[b,n,h*64+d] = (sum_m qp*ctx[m][d]) / (sum_m qp*ksum[m]) ----------------
// grid = (N/8, BH_), block = (64, 8), dyn smem = (256*64 + 256) floats
__global__ void attn_out_kernel(const float* __restrict__ Qp,
                                const float* __restrict__ ctx,
                                const float* __restrict__ ksum,
                                float* __restrict__ out) {
    extern __shared__ float sh[];
    float* ctx_sh = sh;                 // [256*64]
    float* ks_sh  = sh + M_ * DH_;
    const int bh = blockIdx.y;
    const int b = bh >> 4, h = bh & 15;
    const int tid = threadIdx.y * 64 + threadIdx.x;

    for (int i = tid; i < M_ * DH_; i += 512)
        ctx_sh[i] = ctx[(size_t)bh * M_ * DH_ + i];
    if (tid < M_) ks_sh[tid] = ksum[bh * M_ + tid];
    __syncthreads();

    const int n = blockIdx.x * 8 + threadIdx.y;
    const int d = threadIdx.x;
    const float* qp = Qp + ((size_t)bh * N_ + n) * M_;
    float acc = 0.f, den = 0.f;
    #pragma unroll 8
    for (int m = 0; m < M_; m++) {
        float q = qp[m];
        acc += q * ctx_sh[m * 64 + d];
        den += q * ks_sh[m];
    }
    out[((size_t)b * N_ + n) * D_ + h * DH_ + d] = acc / den;
}

// ---------------- LN(X + Res) * g + b ----------------
// grid = RTOT_, block = 256 (4 cols/thread)
__global__ void ln_kernel(const float* __restrict__ X,
                          const float* __restrict__ Res,
                          const float* __restrict__ g,
                          const float* __restrict__ be,
                          float* __restrict__ out) {
    const int row = blockIdx.x;
    const float* x = X + (size_t)row * D_;
    const float* r = Res + (size_t)row * D_;
    const int t = threadIdx.x;
    float v[4]; float s = 0.f, ss = 0.f;
    #pragma unroll
    for (int i = 0; i < 4; i++) {
        int c = t + i * 256;
        v[i] = x[c] + r[c];
        s += v[i]; ss += v[i] * v[i];
    }
    __shared__ float rs[256], rss[256];
    rs[t] = s; rss[t] = ss;
    __syncthreads();
    for (int o = 128; o >= 1; o >>= 1) {
        if (t < o) { rs[t] += rs[t + o]; rss[t] += rss[t + o]; }
        __syncthreads();
    }
    const float mean = rs[0] * (1.f / D_);
    const float var = rss[0] * (1.f / D_) - mean * mean;
    const float inv = rsqrtf(var + LNEPS_);
    #pragma unroll
    for (int i = 0; i < 4; i++) {
        int c = t + i * 256;
        out[(size_t)row * D_ + c] = (v[i] - mean) * inv * g[c] + be[c];
    }
}

// ---------------- host launcher ----------------
extern "C" void kernel_launch(void* const* d_in, const int* in_sizes, int n_in,
                              void* d_out, int out_size) {
    const float* video = (const float*)d_in[0];
    const float* Wq = (const float*)d_in[1];
    const float* bq = (const float*)d_in[2];
    const float* Wk = (const float*)d_in[3];
    const float* bk = (const float*)d_in[4];
    const float* Wv = (const float*)d_in[5];
    const float* bv = (const float*)d_in[6];
    const float* Wo = (const float*)d_in[7];
    const float* bo = (const float*)d_in[8];
    const float* proj = (const float*)d_in[9];
    const float* W1 = (const float*)d_in[10];
    const float* b1 = (const float*)d_in[11];
    const float* W2 = (const float*)d_in[12];
    const float* b2 = (const float*)d_in[13];
    const float* g2 = (const float*)d_in[14];
    const float* be2 = (const float*)d_in[15];
    const float* g3 = (const float*)d_in[16];
    const float* be3 = (const float*)d_in[17];
    float* out = (float*)d_out;

    float *Q, *K, *V, *PQ, *PK, *CTX, *KS, *BHM, *HH;
    cudaGetSymbolAddress((void**)&Q,  g_Q);
    cudaGetSymbolAddress((void**)&K,  g_K);
    cudaGetSymbolAddress((void**)&V,  g_V);
    cudaGetSymbolAddress((void**)&PQ, g_phiQ);
    cudaGetSymbolAddress((void**)&PK, g_phiK);
    cudaGetSymbolAddress((void**)&CTX, g_ctx);
    cudaGetSymbolAddress((void**)&KS, g_ksum);
    cudaGetSymbolAddress((void**)&BHM, g_bhmax);
    cudaGetSymbolAddress((void**)&HH, g_H);

    // 1) QKV projections
    dim3 gQKV(D_ / 128, RTOT_ / 128);
    sgemm_bias_kernel<false><<<gQKV, 256>>>(video, Wq, bq, Q, D_, D_);
    sgemm_bias_kernel<false><<<gQKV, 256>>>(video, Wk, bk, K, D_, D_);
    sgemm_bias_kernel<false><<<gQKV, 256>>>(video, Wv, bv, V, D_, D_);

    // 2) phi projections (raw xp)
    dim3 gPhi(M_ / 64, N_ / 64, BH_);
    phi_gemm_kernel<<<gPhi, 256>>>(Q, proj, PQ);
    phi_gemm_kernel<<<gPhi, 256>>>(K, proj, PK);

    // 3) key stabilizer: per-(b,h) max over raw xp_k
    bhmax_kernel<<<BH_, 256>>>(PK, BHM);

    // 4) exp finalize
    phi_finalize_kernel<true ><<<BH_ * N_, 256>>>(PQ, Q, nullptr);
    phi_finalize_kernel<false><<<BH_ * N_, 256>>>(PK, K, BHM);

    // 5) k_sum
    ksum_kernel<<<BH_, 256>>>(PK, KS);

    // 6) ctx = kp^T @ v  (zero + atomic partials over 8 n-splits)
    zero_kernel<<<(BH_ * M_ * DH_ + 255) / 256, 256>>>(CTX, BH_ * M_ * DH_);
    ctx_kernel<<<dim3(8, BH_), dim3(64, 4)>>>(PK, V, CTX);

    // 7) out = (qp @ ctx) / (qp @ k_sum), written in [b,n,h*dh] layout (reuse Q)
    const int smem = (M_ * DH_ + M_) * sizeof(float);
    cudaFuncSetAttribute(attn_out_kernel, cudaFuncAttributeMaxDynamicSharedMemorySize, smem);
    attn_out_kernel<<<dim3(N_ / 8, BH_), dim3(64, 8), smem>>>(PQ, CTX, KS, Q);

    // 8) output projection (reuse K as attn buffer)
    sgemm_bias_kernel<false><<<gQKV, 256>>>(Q, Wo, bo, K, D_, D_);

    // 9) x = LN(video + attn) (reuse V)
    ln_kernel<<<RTOT_, 256>>>(K, video, g2, be2, V);

    // 10) ffn hidden = relu(x @ W1^T + b1)
    sgemm_bias_kernel<true><<<dim3(DFF_ / 128, RTOT_ / 128), 256>>>(V, W1, b1, HH, D_, DFF_);

    // 11) ffn out = hidden @ W2^T + b2 (reuse Q)
    sgemm_bias_kernel<false><<<dim3(D_ / 128, RTOT_ / 128), 256>>>(HH, W2, b2, Q, DFF_, D_);

    // 12) final LN -> d_out
    ln_kernel<<<RTOT_, 256>>>(Q, V, g3, be3, out);
}

// round 8
// speedup vs baseline: 1.6388x; 1.6388x over previous
#include <cuda_runtime.h>
#include <cuda_bf16.h>
#include <math.h>
#include <stdint.h>

#define B_    4
#define N_    4096
#define D_    1024
#define H_    16
#define DH_   64
#define M_    256
#define DFF_  4096
#define RTOT_ (B_*N_)     // 16384
#define BH_   (B_*H_)     // 64

#define NORM_   0.35355339059327373f   // 64^-0.25
#define DIAGF_  0.0625f                // 0.5 * 64^-0.5
#define RATIO_  0.0625f                // 256^-0.5
#define EPSK_   1e-4f
#define LNEPS_  1e-5f

// ---------------- scratch (static device globals; no allocation) ----------------
__device__ float g_Q[RTOT_ * D_];            // Q acts -> attn-ctx -> ffn out
__device__ float g_K[RTOT_ * D_];            // K acts -> attn (post-Wo)
__device__ float g_V[RTOT_ * D_];            // V acts -> x (post-LN1)
__device__ float g_phiQ[BH_ * N_ * M_];      // xp_q -> qp
__device__ float g_phiK[BH_ * N_ * M_];      // xp_k -> kp
__device__ float g_ctx[BH_ * M_ * DH_];
__device__ float g_ksum[BH_ * M_];
__device__ float g_bhmax[BH_];
__device__ float g_H[RTOT_ * DFF_];          // ffn hidden

// ---------------- tf32 helpers ----------------
__device__ __forceinline__ uint32_t f2tf32(float x) {
    uint32_t r;
    asm("cvt.rna.tf32.f32 %0, %1;" : "=r"(r) : "f"(x));
    return r;
}

__device__ __forceinline__ void mma_tf32(float c[4],
                                         const uint32_t a[4],
                                         const uint32_t b[2]) {
    asm volatile(
        "mma.sync.aligned.m16n8k8.row.col.f32.tf32.tf32.f32 "
        "{%0,%1,%2,%3}, {%4,%5,%6,%7}, {%8,%9}, {%0,%1,%2,%3};"
        : "+f"(c[0]), "+f"(c[1]), "+f"(c[2]), "+f"(c[3])
        : "r"(a[0]), "r"(a[1]), "r"(a[2]), "r"(a[3]), "r"(b[0]), "r"(b[1]));
}

// ---------------- tf32 tensor-core GEMM: C = A @ W^T + bias (opt ReLU) ----------------
// A: [rows x K] row-major fp32, W: [Ncols x K] row-major fp32, C: [rows x Ncols] fp32
// Block tile 128x128, BK=16, 256 threads (8 warps), warp tile 64x32.
// grid = (Ncols/128, rows/128). Requires rows%128==0, Ncols%128==0, K%16==0.
#define SMS 20   // smem row stride (floats); stride%4==0 (float4-aligned), banks conflict-free
template<bool RELU>
__global__ __launch_bounds__(256)
void tgemm_bias_kernel(const float* __restrict__ A,
                       const float* __restrict__ W,
                       const float* __restrict__ bias,
                       float* __restrict__ C,
                       int K, int Ncols) {
    __shared__ uint32_t As[128 * SMS];
    __shared__ uint32_t Ws[128 * SMS];

    const int row0 = blockIdx.y * 128;
    const int col0 = blockIdx.x * 128;
    const int tid  = threadIdx.x;
    const int wid  = tid >> 5;
    const int lane = tid & 31;
    const int wm = (wid >> 2) * 64;     // 0 / 64
    const int wn = (wid & 3) * 32;      // 0/32/64/96

    // global-load mapping: each thread loads 2 rows x 4 consecutive k
    const int glr = tid >> 2;           // 0..63
    const int glk = (tid & 3) * 4;      // 0,4,8,12

    const int lr = lane >> 2;           // 0..7
    const int kq = lane & 3;            // 0..3

    float acc[4][4][4];
    #pragma unroll
    for (int mi = 0; mi < 4; mi++)
        #pragma unroll
        for (int ni = 0; ni < 4; ni++)
            #pragma unroll
            for (int e = 0; e < 4; e++) acc[mi][ni][e] = 0.f;

    for (int k0 = 0; k0 < K; k0 += 16) {
        // load A,W tiles (fp32 -> tf32 at store)
        #pragma unroll
        for (int r = 0; r < 2; r++) {
            const int m = glr + r * 64;
            float4 av = *(const float4*)&A[(size_t)(row0 + m) * K + k0 + glk];
            uint4 at;
            at.x = f2tf32(av.x); at.y = f2tf32(av.y);
            at.z = f2tf32(av.z); at.w = f2tf32(av.w);
            *(uint4*)&As[m * SMS + glk] = at;
            float4 wv = *(const float4*)&W[(size_t)(col0 + m) * K + k0 + glk];
            uint4 wt;
            wt.x = f2tf32(wv.x); wt.y = f2tf32(wv.y);
            wt.z = f2tf32(wv.z); wt.w = f2tf32(wv.w);
            *(uint4*)&Ws[m * SMS + glk] = wt;
        }
        __syncthreads();

        #pragma unroll
        for (int ks = 0; ks < 16; ks += 8) {
            uint32_t a[4][4], b[4][2];
            #pragma unroll
            for (int mi = 0; mi < 4; mi++) {
                const int r = wm + mi * 16 + lr;
                a[mi][0] = As[r * SMS + ks + kq];
                a[mi][1] = As[(r + 8) * SMS + ks + kq];
                a[mi][2] = As[r * SMS + ks + kq + 4];
                a[mi][3] = As[(r + 8) * SMS + ks + kq + 4];
            }
            #pragma unroll
            for (int ni = 0; ni < 4; ni++) {
                const int c = wn + ni * 8 + lr;
                b[ni][0] = Ws[c * SMS + ks + kq];
                b[ni][1] = Ws[c * SMS + ks + kq + 4];
            }
            #pragma unroll
            for (int mi = 0; mi < 4; mi++)
                #pragma unroll
                for (int ni = 0; ni < 4; ni++)
                    mma_tf32(acc[mi][ni], a[mi], b[ni]);
        }
        __syncthreads();
    }

    // epilogue: c0 (r0,c), c1 (r0,c+1), c2 (r1,c), c3 (r1,c+1)
    const int crow = lane >> 2;
    const int ccol = (lane & 3) * 2;
    #pragma unroll
    for (int mi = 0; mi < 4; mi++) {
        const int r0 = row0 + wm + mi * 16 + crow;
        #pragma unroll
        for (int ni = 0; ni < 4; ni++) {
            const int c = col0 + wn + ni * 8 + ccol;
            const float b0 = bias[c], b1 = bias[c + 1];
            float2 v0, v1;
            v0.x = acc[mi][ni][0] + b0; v0.y = acc[mi][ni][1] + b1;
            v1.x = acc[mi][ni][2] + b0; v1.y = acc[mi][ni][3] + b1;
            if (RELU) {
                v0.x = fmaxf(v0.x, 0.f); v0.y = fmaxf(v0.y, 0.f);
                v1.x = fmaxf(v1.x, 0.f); v1.y = fmaxf(v1.y, 0.f);
            }
            *(float2*)&C[(size_t)r0 * Ncols + c] = v0;
            *(float2*)&C[(size_t)(r0 + 8) * Ncols + c] = v1;
        }
    }
}

// ---------------- phi GEMM: xp[bh][n][m] = NORM * sum_d Act[b,n,h*64+d]*proj[m][d] ----------------
// grid = (M/64=4, N/64=64, BH=64), block = 256
__global__ void phi_gemm_kernel(const float* __restrict__ Act,
                                const float* __restrict__ proj,
                                float* __restrict__ Xp) {
    const int z = blockIdx.z;            // bh
    const int b = z >> 4, h = z & 15;
    const float* A = Act + (size_t)b * N_ * D_ + h * DH_;   // rows stride D_
    float* C = Xp + (size_t)z * N_ * M_;

    __shared__ float As[16][65];
    __shared__ float Ws[16][65];
    const int row0 = blockIdx.y * 64;
    const int col0 = blockIdx.x * 64;
    const int tid = threadIdx.x;
    const int lk = tid & 15, lm = tid >> 4;
    const int tx = tid & 15, ty = tid >> 4;
    float acc[4][4];
    #pragma unroll
    for (int i = 0; i < 4; i++)
        #pragma unroll
        for (int j = 0; j < 4; j++) acc[i][j] = 0.f;

    for (int k0 = 0; k0 < DH_; k0 += 16) {
        #pragma unroll
        for (int i = 0; i < 4; i++) {
            int m = lm + i * 16;
            As[lk][m] = A[(size_t)(row0 + m) * D_ + k0 + lk];
            Ws[lk][m] = proj[(size_t)(col0 + m) * DH_ + k0 + lk];
        }
        __syncthreads();
        #pragma unroll
        for (int k = 0; k < 16; k++) {
            float a[4], bb[4];
            #pragma unroll
            for (int i = 0; i < 4; i++) a[i] = As[k][ty * 4 + i];
            #pragma unroll
            for (int j = 0; j < 4; j++) bb[j] = Ws[k][tx * 4 + j];
            #pragma unroll
            for (int i = 0; i < 4; i++)
                #pragma unroll
                for (int j = 0; j < 4; j++)
                    acc[i][j] += a[i] * bb[j];
        }
        __syncthreads();
    }
    #pragma unroll
    for (int i = 0; i < 4; i++) {
        int r = row0 + ty * 4 + i;
        #pragma unroll
        for (int j = 0; j < 4; j++)
            C[(size_t)r * M_ + col0 + tx * 4 + j] = acc[i][j] * NORM_;
    }
}

// ---------------- per-(b,h) global max over raw xp ----------------
__global__ void bhmax_kernel(const float* __restrict__ Xp, float* __restrict__ outMax) {
    const int bh = blockIdx.x;
    const float4* p = (const float4*)(Xp + (size_t)bh * N_ * M_);
    const int tot = N_ * M_ / 4;
    float m = -3.4e38f;
    for (int i = threadIdx.x; i < tot; i += 256) {
        float4 v = p[i];
        m = fmaxf(m, fmaxf(fmaxf(v.x, v.y), fmaxf(v.z, v.w)));
    }
    __shared__ float red[256];
    red[threadIdx.x] = m;
    __syncthreads();
    for (int o = 128; o >= 1; o >>= 1) {
        if (threadIdx.x < o) red[threadIdx.x] = fmaxf(red[threadIdx.x], red[threadIdx.x + o]);
        __syncthreads();
    }
    if (threadIdx.x == 0) outMax[bh] = red[0];
}

// ---------------- finalize: xp -> RATIO*(exp(xp - diag - stab)+eps) ----------------
// grid = BH_*N_ blocks, block = 256 (one thread per m)
template<bool ISQ>
__global__ void phi_finalize_kernel(float* __restrict__ Xp,
                                    const float* __restrict__ Act,
                                    const float* __restrict__ bhmaxArr) {
    const int row = blockIdx.x;          // bh*N + n
    const int bh = row >> 12;
    const int n  = row & (N_ - 1);
    const int b = bh >> 4, h = bh & 15;
    const int t = threadIdx.x;
    __shared__ float red[256];

    const float* x = Act + ((size_t)b * N_ + n) * D_ + h * DH_;
    float ss = 0.f;
    if (t < 64) { float v = x[t]; ss = v * v; }
    red[t] = ss;
    __syncthreads();
    for (int o = 32; o >= 1; o >>= 1) {
        if (t < o) red[t] += red[t + o];
        __syncthreads();
    }
    const float diag = red[0] * DIAGF_;
    __syncthreads();

    float xp = Xp[(size_t)row * M_ + t];
    float stab;
    if (ISQ) {
        red[t] = xp;
        __syncthreads();
        for (int o = 128; o >= 1; o >>= 1) {
            if (t < o) red[t] = fmaxf(red[t], red[t + o]);
            __syncthreads();
        }
        stab = red[0];
    } else {
        stab = bhmaxArr[bh];
    }
    Xp[(size_t)row * M_ + t] = RATIO_ * (__expf(xp - diag - stab) + EPSK_);
}

// ---------------- k_sum[bh][m] = sum_n kp[bh][n][m] ----------------
__global__ void ksum_kernel(const float* __restrict__ Kp, float* __restrict__ ks) {
    const int bh = blockIdx.x;
    const float* p = Kp + (size_t)bh * N_ * M_ + threadIdx.x;
    float s = 0.f;
    #pragma unroll 8
    for (int n = 0; n < N_; n++) s += p[(size_t)n * M_];
    ks[bh * M_ + threadIdx.x] = s;
}

__global__ void zero_kernel(float* __restrict__ p, int n) {
    int i = blockIdx.x * 256 + threadIdx.x;
    if (i < n) p[i] = 0.f;
}

// ---------------- ctx[bh][m][d] = sum_n kp[bh][n][m] * v[b,n,h*64+d] ----------------
// grid = (8 splits, BH_), block = (64, 4). float atomics into zeroed ctx.
__global__ void ctx_kernel(const float* __restrict__ Kp,
                           const float* __restrict__ V,
                           float* __restrict__ ctx) {
    const int bh = blockIdx.y;
    const int b = bh >> 4, h = bh & 15;
    const int d = threadIdx.x;
    const int tg = threadIdx.y;          // 0..3 -> m block of 64
    const int n0 = blockIdx.x * (N_ / 8);

    float acc[64];
    #pragma unroll
    for (int i = 0; i < 64; i++) acc[i] = 0.f;

    const float* kp = Kp + (size_t)bh * N_ * M_ + tg * 64;
    const float* v  = V + (size_t)b * N_ * D_ + h * DH_ + d;

    for (int n = n0; n < n0 + N_ / 8; n++) {
        float vv = v[(size_t)n * D_];
        const float* kr = kp + (size_t)n * M_;
        #pragma unroll
        for (int i = 0; i < 64; i++) acc[i] += kr[i] * vv;
    }
    float* cb = ctx + (size_t)bh * M_ * DH_ + (tg * 64) * DH_ + d;
    #pragma unroll
    for (int i = 0; i < 64; i++) atomicAdd(cb + i * DH_, acc[i]);
}

// ---------------- out[b,n,h*64+d] = (sum_m qp*ctx[m][d]) / (sum_m qp*ksum[m]) ----------------
// grid = (N/8, BH_), block = (64, 8), dyn smem = (256*64 + 256) floats
__global__ void attn_out_kernel(const float* __restrict__ Qp,
                                const float* __restrict__ ctx,
                                const float* __restrict__ ksum,
                                float* __restrict__ out) {
    extern __shared__ float sh[];
    float* ctx_sh = sh;                 // [256*64]
    float* ks_sh  = sh + M_ * DH_;
    const int bh = blockIdx.y;
    const int b = bh >> 4, h = bh & 15;
    const int tid = threadIdx.y * 64 + threadIdx.x;

    for (int i = tid; i < M_ * DH_; i += 512)
        ctx_sh[i] = ctx[(size_t)bh * M_ * DH_ + i];
    if (tid < M_) ks_sh[tid] = ksum[bh * M_ + tid];
    __syncthreads();

    const int n = blockIdx.x * 8 + threadIdx.y;
    const int d = threadIdx.x;
    const float* qp = Qp + ((size_t)bh * N_ + n) * M_;
    float acc = 0.f, den = 0.f;
    #pragma unroll 8
    for (int m = 0; m < M_; m++) {
        float q = qp[m];
        acc += q * ctx_sh[m * 64 + d];
        den += q * ks_sh[m];
    }
    out[((size_t)b * N_ + n) * D_ + h * DH_ + d] = acc / den;
}

// ---------------- LN(X + Res) * g + b ----------------
// grid = RTOT_, block = 256 (4 cols/thread)
__global__ void ln_kernel(const float* __restrict__ X,
                          const float* __restrict__ Res,
                          const float* __restrict__ g,
                          const float* __restrict__ be,
                          float* __restrict__ out) {
    const int row = blockIdx.x;
    const float* x = X + (size_t)row * D_;
    const float* r = Res + (size_t)row * D_;
    const int t = threadIdx.x;
    float v[4]; float s = 0.f, ss = 0.f;
    #pragma unroll
    for (int i = 0; i < 4; i++) {
        int c = t + i * 256;
        v[i] = x[c] + r[c];
        s += v[i]; ss += v[i] * v[i];
    }
    __shared__ float rs[256], rss[256];
    rs[t] = s; rss[t] = ss;
    __syncthreads();
    for (int o = 128; o >= 1; o >>= 1) {
        if (t < o) { rs[t] += rs[t + o]; rss[t] += rss[t + o]; }
        __syncthreads();
    }
    const float mean = rs[0] * (1.f / D_);
    const float var = rss[0] * (1.f / D_) - mean * mean;
    const float inv = rsqrtf(var + LNEPS_);
    #pragma unroll
    for (int i = 0; i < 4; i++) {
        int c = t + i * 256;
        out[(size_t)row * D_ + c] = (v[i] - mean) * inv * g[c] + be[c];
    }
}

// ---------------- host launcher ----------------
extern "C" void kernel_launch(void* const* d_in, const int* in_sizes, int n_in,
                              void* d_out, int out_size) {
    const float* video = (const float*)d_in[0];
    const float* Wq = (const float*)d_in[1];
    const float* bq = (const float*)d_in[2];
    const float* Wk = (const float*)d_in[3];
    const float* bk = (const float*)d_in[4];
    const float* Wv = (const float*)d_in[5];
    const float* bv = (const float*)d_in[6];
    const float* Wo = (const float*)d_in[7];
    const float* bo = (const float*)d_in[8];
    const float* proj = (const float*)d_in[9];
    const float* W1 = (const float*)d_in[10];
    const float* b1 = (const float*)d_in[11];
    const float* W2 = (const float*)d_in[12];
    const float* b2 = (const float*)d_in[13];
    const float* g2 = (const float*)d_in[14];
    const float* be2 = (const float*)d_in[15];
    const float* g3 = (const float*)d_in[16];
    const float* be3 = (const float*)d_in[17];
    float* out = (float*)d_out;

    float *Q, *K, *V, *PQ, *PK, *CTX, *KS, *BHM, *HH;
    cudaGetSymbolAddress((void**)&Q,  g_Q);
    cudaGetSymbolAddress((void**)&K,  g_K);
    cudaGetSymbolAddress((void**)&V,  g_V);
    cudaGetSymbolAddress((void**)&PQ, g_phiQ);
    cudaGetSymbolAddress((void**)&PK, g_phiK);
    cudaGetSymbolAddress((void**)&CTX, g_ctx);
    cudaGetSymbolAddress((void**)&KS, g_ksum);
    cudaGetSymbolAddress((void**)&BHM, g_bhmax);
    cudaGetSymbolAddress((void**)&HH, g_H);

    // 1) QKV projections (tf32 tensor cores)
    dim3 gQKV(D_ / 128, RTOT_ / 128);
    tgemm_bias_kernel<false><<<gQKV, 256>>>(video, Wq, bq, Q, D_, D_);
    tgemm_bias_kernel<false><<<gQKV, 256>>>(video, Wk, bk, K, D_, D_);
    tgemm_bias_kernel<false><<<gQKV, 256>>>(video, Wv, bv, V, D_, D_);

    // 2) phi projections (raw xp) — fp32 for exp-path precision
    dim3 gPhi(M_ / 64, N_ / 64, BH_);
    phi_gemm_kernel<<<gPhi, 256>>>(Q, proj, PQ);
    phi_gemm_kernel<<<gPhi, 256>>>(K, proj, PK);

    // 3) key stabilizer: per-(b,h) max over raw xp_k
    bhmax_kernel<<<BH_, 256>>>(PK, BHM);

    // 4) exp finalize
    phi_finalize_kernel<true ><<<BH_ * N_, 256>>>(PQ, Q, nullptr);
    phi_finalize_kernel<false><<<BH_ * N_, 256>>>(PK, K, BHM);

    // 5) k_sum
    ksum_kernel<<<BH_, 256>>>(PK, KS);

    // 6) ctx = kp^T @ v  (zero + atomic partials over 8 n-splits)
    zero_kernel<<<(BH_ * M_ * DH_ + 255) / 256, 256>>>(CTX, BH_ * M_ * DH_);
    ctx_kernel<<<dim3(8, BH_), dim3(64, 4)>>>(PK, V, CTX);

    // 7) out = (qp @ ctx) / (qp @ k_sum), written in [b,n,h*dh] layout (reuse Q)
    const int smem = (M_ * DH_ + M_) * sizeof(float);
    cudaFuncSetAttribute(attn_out_kernel, cudaFuncAttributeMaxDynamicSharedMemorySize, smem);
    attn_out_kernel<<<dim3(N_ / 8, BH_), dim3(64, 8), smem>>>(PQ, CTX, KS, Q);

    // 8) output projection (reuse K as attn buffer)
    tgemm_bias_kernel<false><<<gQKV, 256>>>(Q, Wo, bo, K, D_, D_);

    // 9) x = LN(video + attn) (reuse V)
    ln_kernel<<<RTOT_, 256>>>(K, video, g2, be2, V);

    // 10) ffn hidden = relu(x @ W1^T + b1)
    tgemm_bias_kernel<true><<<dim3(DFF_ / 128, RTOT_ / 128), 256>>>(V, W1, b1, HH, D_, DFF_);

    // 11) ffn out = hidden @ W2^T + b2 (reuse Q)
    tgemm_bias_kernel<false><<<dim3(D_ / 128, RTOT_ / 128), 256>>>(HH, W2, b2, Q, DFF_, D_);

    // 12) final LN -> d_out
    ln_kernel<<<RTOT_, 256>>>(Q, V, g3, be3, out);
}

// round 9
// speedup vs baseline: 1.6879x; 1.0300x over previous
#include <cuda_runtime.h>
#include <cuda_bf16.h>
#include <math.h>
#include <stdint.h>

#define B_    4
#define N_    4096
#define D_    1024
#define H_    16
#define DH_   64
#define M_    256
#define DFF_  4096
#define RTOT_ (B_*N_)     // 16384
#define BH_   (B_*H_)     // 64

#define NORM_   0.35355339059327373f   // 64^-0.25
#define DIAGF_  0.0625f                // 0.5 * 64^-0.5
#define RATIO_  0.0625f                // 256^-0.5
#define EPSK_   1e-4f
#define LNEPS_  1e-5f

// ---------------- scratch (static device globals; no allocation) ----------------
__device__ float g_Q[RTOT_ * D_];            // Q acts -> attn-ctx -> ffn out
__device__ float g_K[RTOT_ * D_];            // K acts -> attn (post-Wo)
__device__ float g_V[RTOT_ * D_];            // V acts -> x (post-LN1)
__device__ float g_phiQ[BH_ * N_ * M_];      // xp_q -> qp
__device__ float g_phiK[BH_ * N_ * M_];      // xp_k -> kp
__device__ float g_ctx[BH_ * M_ * DH_];
__device__ float g_ksum[BH_ * M_];
__device__ float g_bhmax[BH_];
__device__ float g_H[RTOT_ * DFF_];          // ffn hidden

// ---------------- tf32 helpers ----------------
__device__ __forceinline__ uint32_t f2tf32(float x) {
    uint32_t r;
    asm("cvt.rna.tf32.f32 %0, %1;" : "=r"(r) : "f"(x));
    return r;
}

__device__ __forceinline__ void mma_tf32(float c[4],
                                         const uint32_t a[4],
                                         const uint32_t b[2]) {
    asm volatile(
        "mma.sync.aligned.m16n8k8.row.col.f32.tf32.tf32.f32 "
        "{%0,%1,%2,%3}, {%4,%5,%6,%7}, {%8,%9}, {%0,%1,%2,%3};"
        : "+f"(c[0]), "+f"(c[1]), "+f"(c[2]), "+f"(c[3])
        : "r"(a[0]), "r"(a[1]), "r"(a[2]), "r"(a[3]), "r"(b[0]), "r"(b[1]));
}

// ---------------- tf32 tensor-core GEMM (pipelined): C = A @ W^T + bias (opt ReLU) ----------------
// A: [rows x K] row-major fp32, W: [Ncols x K] row-major fp32, C: [rows x Ncols] fp32
// Block tile 128x128, BK=32, double-buffered smem, register prefetch.
// 256 threads (8 warps), warp tile 64x32. grid = (Ncols/128, rows/128).
// Requires rows%128==0, Ncols%128==0, K%32==0.
#define SMS2 36   // smem row stride (u32); fragment LDS banks lr*36+kq ≡ lr*4+kq mod 32 — all distinct
template<bool RELU>
__global__ __launch_bounds__(256)
void tgemm_bias_kernel(const float* __restrict__ A,
                       const float* __restrict__ W,
                       const float* __restrict__ bias,
                       float* __restrict__ C,
                       int K, int Ncols) {
    __shared__ uint32_t As[2][128 * SMS2];
    __shared__ uint32_t Ws[2][128 * SMS2];

    const int row0 = blockIdx.y * 128;
    const int col0 = blockIdx.x * 128;
    const int tid  = threadIdx.x;
    const int wid  = tid >> 5;
    const int lane = tid & 31;
    const int wm = (wid >> 2) * 64;     // 0 / 64
    const int wn = (wid & 3) * 32;      // 0/32/64/96

    // global-load mapping: 8 threads per row (32 floats), 32 row-groups of 4
    const int glr = tid >> 3;           // 0..31
    const int glk = (tid & 7) * 4;      // 0,4,...,28

    const int lr = lane >> 2;           // 0..7
    const int kq = lane & 3;            // 0..3

    float acc[4][4][4];
    #pragma unroll
    for (int mi = 0; mi < 4; mi++)
        #pragma unroll
        for (int ni = 0; ni < 4; ni++)
            #pragma unroll
            for (int e = 0; e < 4; e++) acc[mi][ni][e] = 0.f;

    float4 pa[4], pw[4];                // prefetch registers

    // prologue: load tile 0
    #pragma unroll
    for (int r = 0; r < 4; r++) {
        const int m = glr + r * 32;
        pa[r] = *(const float4*)&A[(size_t)(row0 + m) * K + glk];
        pw[r] = *(const float4*)&W[(size_t)(col0 + m) * K + glk];
    }
    #pragma unroll
    for (int r = 0; r < 4; r++) {
        const int m = glr + r * 32;
        uint4 at;
        at.x = f2tf32(pa[r].x); at.y = f2tf32(pa[r].y);
        at.z = f2tf32(pa[r].z); at.w = f2tf32(pa[r].w);
        *(uint4*)&As[0][m * SMS2 + glk] = at;
        uint4 wt;
        wt.x = f2tf32(pw[r].x); wt.y = f2tf32(pw[r].y);
        wt.z = f2tf32(pw[r].z); wt.w = f2tf32(pw[r].w);
        *(uint4*)&Ws[0][m * SMS2 + glk] = wt;
    }
    __syncthreads();

    int p = 0;
    for (int k0 = 0; k0 < K; k0 += 32) {
        const bool has_next = (k0 + 32 < K);
        // issue next tile's global loads early — latency hides under the MMAs below
        if (has_next) {
            #pragma unroll
            for (int r = 0; r < 4; r++) {
                const int m = glr + r * 32;
                pa[r] = *(const float4*)&A[(size_t)(row0 + m) * K + k0 + 32 + glk];
                pw[r] = *(const float4*)&W[(size_t)(col0 + m) * K + k0 + 32 + glk];
            }
        }

        // compute current buffer: 4 ks-steps x 16 MMAs
        #pragma unroll
        for (int ks = 0; ks < 32; ks += 8) {
            uint32_t a[4][4], b[4][2];
            #pragma unroll
            for (int mi = 0; mi < 4; mi++) {
                const int r = wm + mi * 16 + lr;
                a[mi][0] = As[p][r * SMS2 + ks + kq];
                a[mi][1] = As[p][(r + 8) * SMS2 + ks + kq];
                a[mi][2] = As[p][r * SMS2 + ks + kq + 4];
                a[mi][3] = As[p][(r + 8) * SMS2 + ks + kq + 4];
            }
            #pragma unroll
            for (int ni = 0; ni < 4; ni++) {
                const int c = wn + ni * 8 + lr;
                b[ni][0] = Ws[p][c * SMS2 + ks + kq];
                b[ni][1] = Ws[p][c * SMS2 + ks + kq + 4];
            }
            #pragma unroll
            for (int mi = 0; mi < 4; mi++)
                #pragma unroll
                for (int ni = 0; ni < 4; ni++)
                    mma_tf32(acc[mi][ni], a[mi], b[ni]);
        }

        if (has_next) {
            // store prefetched tile to the other buffer; one barrier per 32-k slice
            #pragma unroll
            for (int r = 0; r < 4; r++) {
                const int m = glr + r * 32;
                uint4 at;
                at.x = f2tf32(pa[r].x); at.y = f2tf32(pa[r].y);
                at.z = f2tf32(pa[r].z); at.w = f2tf32(pa[r].w);
                *(uint4*)&As[p ^ 1][m * SMS2 + glk] = at;
                uint4 wt;
                wt.x = f2tf32(pw[r].x); wt.y = f2tf32(pw[r].y);
                wt.z = f2tf32(pw[r].z); wt.w = f2tf32(pw[r].w);
                *(uint4*)&Ws[p ^ 1][m * SMS2 + glk] = wt;
            }
            __syncthreads();
            p ^= 1;
        }
    }

    // epilogue: c0 (r0,c), c1 (r0,c+1), c2 (r1,c), c3 (r1,c+1)
    const int crow = lane >> 2;
    const int ccol = (lane & 3) * 2;
    #pragma unroll
    for (int mi = 0; mi < 4; mi++) {
        const int r0 = row0 + wm + mi * 16 + crow;
        #pragma unroll
        for (int ni = 0; ni < 4; ni++) {
            const int c = col0 + wn + ni * 8 + ccol;
            const float b0 = bias[c], b1 = bias[c + 1];
            float2 v0, v1;
            v0.x = acc[mi][ni][0] + b0; v0.y = acc[mi][ni][1] + b1;
            v1.x = acc[mi][ni][2] + b0; v1.y = acc[mi][ni][3] + b1;
            if (RELU) {
                v0.x = fmaxf(v0.x, 0.f); v0.y = fmaxf(v0.y, 0.f);
                v1.x = fmaxf(v1.x, 0.f); v1.y = fmaxf(v1.y, 0.f);
            }
            *(float2*)&C[(size_t)r0 * Ncols + c] = v0;
            *(float2*)&C[(size_t)(r0 + 8) * Ncols + c] = v1;
        }
    }
}

// ---------------- phi GEMM: xp[bh][n][m] = NORM * sum_d Act[b,n,h*64+d]*proj[m][d] ----------------
// grid = (M/64=4, N/64=64, BH=64), block = 256
__global__ void phi_gemm_kernel(const float* __restrict__ Act,
                                const float* __restrict__ proj,
                                float* __restrict__ Xp) {
    const int z = blockIdx.z;            // bh
    const int b = z >> 4, h = z & 15;
    const float* A = Act + (size_t)b * N_ * D_ + h * DH_;   // rows stride D_
    float* C = Xp + (size_t)z * N_ * M_;

    __shared__ float As[16][65];
    __shared__ float Ws[16][65];
    const int row0 = blockIdx.y * 64;
    const int col0 = blockIdx.x * 64;
    const int tid = threadIdx.x;
    const int lk = tid & 15, lm = tid >> 4;
    const int tx = tid & 15, ty = tid >> 4;
    float acc[4][4];
    #pragma unroll
    for (int i = 0; i < 4; i++)
        #pragma unroll
        for (int j = 0; j < 4; j++) acc[i][j] = 0.f;

    for (int k0 = 0; k0 < DH_; k0 += 16) {
        #pragma unroll
        for (int i = 0; i < 4; i++) {
            int m = lm + i * 16;
            As[lk][m] = A[(size_t)(row0 + m) * D_ + k0 + lk];
            Ws[lk][m] = proj[(size_t)(col0 + m) * DH_ + k0 + lk];
        }
        __syncthreads();
        #pragma unroll
        for (int k = 0; k < 16; k++) {
            float a[4], bb[4];
            #pragma unroll
            for (int i = 0; i < 4; i++) a[i] = As[k][ty * 4 + i];
            #pragma unroll
            for (int j = 0; j < 4; j++) bb[j] = Ws[k][tx * 4 + j];
            #pragma unroll
            for (int i = 0; i < 4; i++)
                #pragma unroll
                for (int j = 0; j < 4; j++)
                    acc[i][j] += a[i] * bb[j];
        }
        __syncthreads();
    }
    #pragma unroll
    for (int i = 0; i < 4; i++) {
        int r = row0 + ty * 4 + i;
        #pragma unroll
        for (int j = 0; j < 4; j++)
            C[(size_t)r * M_ + col0 + tx * 4 + j] = acc[i][j] * NORM_;
    }
}

// ---------------- per-(b,h) global max over raw xp ----------------
__global__ void bhmax_kernel(const float* __restrict__ Xp, float* __restrict__ outMax) {
    const int bh = blockIdx.x;
    const float4* p = (const float4*)(Xp + (size_t)bh * N_ * M_);
    const int tot = N_ * M_ / 4;
    float m = -3.4e38f;
    for (int i = threadIdx.x; i < tot; i += 256) {
        float4 v = p[i];
        m = fmaxf(m, fmaxf(fmaxf(v.x, v.y), fmaxf(v.z, v.w)));
    }
    __shared__ float red[256];
    red[threadIdx.x] = m;
    __syncthreads();
    for (int o = 128; o >= 1; o >>= 1) {
        if (threadIdx.x < o) red[threadIdx.x] = fmaxf(red[threadIdx.x], red[threadIdx.x + o]);
        __syncthreads();
    }
    if (threadIdx.x == 0) outMax[bh] = red[0];
}

// ---------------- finalize: xp -> RATIO*(exp(xp - diag - stab)+eps) ----------------
// grid = BH_*N_ blocks, block = 256 (one thread per m)
template<bool ISQ>
__global__ void phi_finalize_kernel(float* __restrict__ Xp,
                                    const float* __restrict__ Act,
                                    const float* __restrict__ bhmaxArr) {
    const int row = blockIdx.x;          // bh*N + n
    const int bh = row >> 12;
    const int n  = row & (N_ - 1);
    const int b = bh >> 4, h = bh & 15;
    const int t = threadIdx.x;
    __shared__ float red[256];

    const float* x = Act + ((size_t)b * N_ + n) * D_ + h * DH_;
    float ss = 0.f;
    if (t < 64) { float v = x[t]; ss = v * v; }
    red[t] = ss;
    __syncthreads();
    for (int o = 32; o >= 1; o >>= 1) {
        if (t < o) red[t] += red[t + o];
        __syncthreads();
    }
    const float diag = red[0] * DIAGF_;
    __syncthreads();

    float xp = Xp[(size_t)row * M_ + t];
    float stab;
    if (ISQ) {
        red[t] = xp;
        __syncthreads();
        for (int o = 128; o >= 1; o >>= 1) {
            if (t < o) red[t] = fmaxf(red[t], red[t + o]);
            __syncthreads();
        }
        stab = red[0];
    } else {
        stab = bhmaxArr[bh];
    }
    Xp[(size_t)row * M_ + t] = RATIO_ * (__expf(xp - diag - stab) + EPSK_);
}

// ---------------- k_sum[bh][m] = sum_n kp[bh][n][m] ----------------
__global__ void ksum_kernel(const float* __restrict__ Kp, float* __restrict__ ks) {
    const int bh = blockIdx.x;
    const float* p = Kp + (size_t)bh * N_ * M_ + threadIdx.x;
    float s = 0.f;
    #pragma unroll 8
    for (int n = 0; n < N_; n++) s += p[(size_t)n * M_];
    ks[bh * M_ + threadIdx.x] = s;
}

__global__ void zero_kernel(float* __restrict__ p, int n) {
    int i = blockIdx.x * 256 + threadIdx.x;
    if (i < n) p[i] = 0.f;
}

// ---------------- ctx[bh][m][d] = sum_n kp[bh][n][m] * v[b,n,h*64+d] ----------------
// grid = (8 splits, BH_), block = (64, 4). float atomics into zeroed ctx.
__global__ void ctx_kernel(const float* __restrict__ Kp,
                           const float* __restrict__ V,
                           float* __restrict__ ctx) {
    const int bh = blockIdx.y;
    const int b = bh >> 4, h = bh & 15;
    const int d = threadIdx.x;
    const int tg = threadIdx.y;          // 0..3 -> m block of 64
    const int n0 = blockIdx.x * (N_ / 8);

    float acc[64];
    #pragma unroll
    for (int i = 0; i < 64; i++) acc[i] = 0.f;

    const float* kp = Kp + (size_t)bh * N_ * M_ + tg * 64;
    const float* v  = V + (size_t)b * N_ * D_ + h * DH_ + d;

    for (int n = n0; n < n0 + N_ / 8; n++) {
        float vv = v[(size_t)n * D_];
        const float* kr = kp + (size_t)n * M_;
        #pragma unroll
        for (int i = 0; i < 64; i++) acc[i] += kr[i] * vv;
    }
    float* cb = ctx + (size_t)bh * M_ * DH_ + (tg * 64) * DH_ + d;
    #pragma unroll
    for (int i = 0; i < 64; i++) atomicAdd(cb + i * DH_, acc[i]);
}

// ---------------- out[b,n,h*64+d] = (sum_m qp*ctx[m][d]) / (sum_m qp*ksum[m]) ----------------
// grid = (N/8, BH_), block = (64, 8), dyn smem = (256*64 + 256) floats
__global__ void attn_out_kernel(const float* __restrict__ Qp,
                                const float* __restrict__ ctx,
                                const float* __restrict__ ksum,
                                float* __restrict__ out) {
    extern __shared__ float sh[];
    float* ctx_sh = sh;                 // [256*64]
    float* ks_sh  = sh + M_ * DH_;
    const int bh = blockIdx.y;
    const int b = bh >> 4, h = bh & 15;
    const int tid = threadIdx.y * 64 + threadIdx.x;

    for (int i = tid; i < M_ * DH_; i += 512)
        ctx_sh[i] = ctx[(size_t)bh * M_ * DH_ + i];
    if (tid < M_) ks_sh[tid] = ksum[bh * M_ + tid];
    __syncthreads();

    const int n = blockIdx.x * 8 + threadIdx.y;
    const int d = threadIdx.x;
    const float* qp = Qp + ((size_t)bh * N_ + n) * M_;
    float acc = 0.f, den = 0.f;
    #pragma unroll 8
    for (int m = 0; m < M_; m++) {
        float q = qp[m];
        acc += q * ctx_sh[m * 64 + d];
        den += q * ks_sh[m];
    }
    out[((size_t)b * N_ + n) * D_ + h * DH_ + d] = acc / den;
}

// ---------------- LN(X + Res) * g + b ----------------
// grid = RTOT_, block = 256 (4 cols/thread)
__global__ void ln_kernel(const float* __restrict__ X,
                          const float* __restrict__ Res,
                          const float* __restrict__ g,
                          const float* __restrict__ be,
                          float* __restrict__ out) {
    const int row = blockIdx.x;
    const float* x = X + (size_t)row * D_;
    const float* r = Res + (size_t)row * D_;
    const int t = threadIdx.x;
    float v[4]; float s = 0.f, ss = 0.f;
    #pragma unroll
    for (int i = 0; i < 4; i++) {
        int c = t + i * 256;
        v[i] = x[c] + r[c];
        s += v[i]; ss += v[i] * v[i];
    }
    __shared__ float rs[256], rss[256];
    rs[t] = s; rss[t] = ss;
    __syncthreads();
    for (int o = 128; o >= 1; o >>= 1) {
        if (t < o) { rs[t] += rs[t + o]; rss[t] += rss[t + o]; }
        __syncthreads();
    }
    const float mean = rs[0] * (1.f / D_);
    const float var = rss[0] * (1.f / D_) - mean * mean;
    const float inv = rsqrtf(var + LNEPS_);
    #pragma unroll
    for (int i = 0; i < 4; i++) {
        int c = t + i * 256;
        out[(size_t)row * D_ + c] = (v[i] - mean) * inv * g[c] + be[c];
    }
}

// ---------------- host launcher ----------------
extern "C" void kernel_launch(void* const* d_in, const int* in_sizes, int n_in,
                              void* d_out, int out_size) {
    const float* video = (const float*)d_in[0];
    const float* Wq = (const float*)d_in[1];
    const float* bq = (const float*)d_in[2];
    const float* Wk = (const float*)d_in[3];
    const float* bk = (const float*)d_in[4];
    const float* Wv = (const float*)d_in[5];
    const float* bv = (const float*)d_in[6];
    const float* Wo = (const float*)d_in[7];
    const float* bo = (const float*)d_in[8];
    const float* proj = (const float*)d_in[9];
    const float* W1 = (const float*)d_in[10];
    const float* b1 = (const float*)d_in[11];
    const float* W2 = (const float*)d_in[12];
    const float* b2 = (const float*)d_in[13];
    const float* g2 = (const float*)d_in[14];
    const float* be2 = (const float*)d_in[15];
    const float* g3 = (const float*)d_in[16];
    const float* be3 = (const float*)d_in[17];
    float* out = (float*)d_out;

    float *Q, *K, *V, *PQ, *PK, *CTX, *KS, *BHM, *HH;
    cudaGetSymbolAddress((void**)&Q,  g_Q);
    cudaGetSymbolAddress((void**)&K,  g_K);
    cudaGetSymbolAddress((void**)&V,  g_V);
    cudaGetSymbolAddress((void**)&PQ, g_phiQ);
    cudaGetSymbolAddress((void**)&PK, g_phiK);
    cudaGetSymbolAddress((void**)&CTX, g_ctx);
    cudaGetSymbolAddress((void**)&KS, g_ksum);
    cudaGetSymbolAddress((void**)&BHM, g_bhmax);
    cudaGetSymbolAddress((void**)&HH, g_H);

    // 1) QKV projections (tf32 tensor cores, pipelined)
    dim3 gQKV(D_ / 128, RTOT_ / 128);
    tgemm_bias_kernel<false><<<gQKV, 256>>>(video, Wq, bq, Q, D_, D_);
    tgemm_bias_kernel<false><<<gQKV, 256>>>(video, Wk, bk, K, D_, D_);
    tgemm_bias_kernel<false><<<gQKV, 256>>>(video, Wv, bv, V, D_, D_);

    // 2) phi projections (raw xp) — fp32 for exp-path precision
    dim3 gPhi(M_ / 64, N_ / 64, BH_);
    phi_gemm_kernel<<<gPhi, 256>>>(Q, proj, PQ);
    phi_gemm_kernel<<<gPhi, 256>>>(K, proj, PK);

    // 3) key stabilizer: per-(b,h) max over raw xp_k
    bhmax_kernel<<<BH_, 256>>>(PK, BHM);

    // 4) exp finalize
    phi_finalize_kernel<true ><<<BH_ * N_, 256>>>(PQ, Q, nullptr);
    phi_finalize_kernel<false><<<BH_ * N_, 256>>>(PK, K, BHM);

    // 5) k_sum
    ksum_kernel<<<BH_, 256>>>(PK, KS);

    // 6) ctx = kp^T @ v  (zero + atomic partials over 8 n-splits)
    zero_kernel<<<(BH_ * M_ * DH_ + 255) / 256, 256>>>(CTX, BH_ * M_ * DH_);
    ctx_kernel<<<dim3(8, BH_), dim3(64, 4)>>>(PK, V, CTX);

    // 7) out = (qp @ ctx) / (qp @ k_sum), written in [b,n,h*dh] layout (reuse Q)
    const int smem = (M_ * DH_ + M_) * sizeof(float);
    cudaFuncSetAttribute(attn_out_kernel, cudaFuncAttributeMaxDynamicSharedMemorySize, smem);
    attn_out_kernel<<<dim3(N_ / 8, BH_), dim3(64, 8), smem>>>(PQ, CTX, KS, Q);

    // 8) output projection (reuse K as attn buffer)
    tgemm_bias_kernel<false><<<gQKV, 256>>>(Q, Wo, bo, K, D_, D_);

    // 9) x = LN(video + attn) (reuse V)
    ln_kernel<<<RTOT_, 256>>>(K, video, g2, be2, V);

    // 10) ffn hidden = relu(x @ W1^T + b1)
    tgemm_bias_kernel<true><<<dim3(DFF_ / 128, RTOT_ / 128), 256>>>(V, W1, b1, HH, D_, DFF_);

    // 11) ffn out = hidden @ W2^T + b2 (reuse Q)
    tgemm_bias_kernel<false><<<dim3(D_ / 128, RTOT_ / 128), 256>>>(HH, W2, b2, Q, DFF_, D_);

    // 12) final LN -> d_out
    ln_kernel<<<RTOT_, 256>>>(Q, V, g3, be3, out);
}

// round 17
// speedup vs baseline: 1.7873x; 1.0589x over previous
#include <cuda_runtime.h>
#include <cuda_bf16.h>
#include <cuda_fp16.h>
#include <math.h>
#include <stdint.h>

#define B_    4
#define N_    4096
#define D_    1024
#define H_    16
#define DH_   64
#define M_    256
#define DFF_  4096
#define RTOT_ (B_*N_)     // 16384
#define BH_   (B_*H_)     // 64

#define NORM_   0.35355339059327373f   // 64^-0.25
#define DIAGF_  0.0625f                // 0.5 * 64^-0.5
#define RATIO_  0.0625f                // 256^-0.5
#define EPSK_   1e-4f
#define LNEPS_  1e-5f

// ---------------- scratch (static device globals; no allocation) ----------------
__device__ float g_Q[RTOT_ * D_];            // Q acts -> attn-ctx -> ffn out
__device__ float g_K[RTOT_ * D_];            // K acts -> attn (post-Wo)
__device__ float g_V[RTOT_ * D_];            // V acts -> x (post-LN1)
__device__ float g_phiQ[BH_ * N_ * M_];      // xp_q -> qp
__device__ float g_phiK[BH_ * N_ * M_];      // xp_k -> kp
__device__ float g_ctx[BH_ * M_ * DH_];
__device__ float g_ksum[BH_ * M_];
__device__ float g_bhmax[BH_];
__device__ float g_H[RTOT_ * DFF_];          // ffn hidden

// ---------------- fp16 helpers ----------------
__device__ __forceinline__ uint32_t f2h2(float lo, float hi) {
    __half2 h = __floats2half2_rn(lo, hi);
    return *(uint32_t*)&h;
}

__device__ __forceinline__ void mma_f16(float c[4],
                                        const uint32_t a[4],
                                        const uint32_t b[2]) {
    asm volatile(
        "mma.sync.aligned.m16n8k16.row.col.f32.f16.f16.f32 "
        "{%0,%1,%2,%3}, {%4,%5,%6,%7}, {%8,%9}, {%0,%1,%2,%3};"
        : "+f"(c[0]), "+f"(c[1]), "+f"(c[2]), "+f"(c[3])
        : "r"(a[0]), "r"(a[1]), "r"(a[2]), "r"(a[3]), "r"(b[0]), "r"(b[1]));
}

// ---------------- fp16 tensor-core GEMM (pipelined): C = A @ W^T + bias (opt ReLU) ----------------
// A: [rows x K] row-major fp32, W: [Ncols x K] row-major fp32, C: [rows x Ncols] fp32
// Block tile 128x128, BK=32 (2 x k16 mma steps), double-buffered smem, register prefetch.
// 256 threads (8 warps), warp tile 64x32. grid = (Ncols/128, rows/128).
// Requires rows%128==0, Ncols%128==0, K%32==0.
// smem stride SMS2=20 half2-units/row: fragment banks (row*20+kq) mod 32 all-distinct.
#define SMS2 20
template<bool RELU>
__global__ __launch_bounds__(256)
void tgemm_bias_kernel(const float* __restrict__ A,
                       const float* __restrict__ W,
                       const float* __restrict__ bias,
                       float* __restrict__ C,
                       int K, int Ncols) {
    __shared__ uint32_t As[2][128 * SMS2];   // half2 units
    __shared__ uint32_t Ws[2][128 * SMS2];

    const int row0 = blockIdx.y * 128;
    const int col0 = blockIdx.x * 128;
    const int tid  = threadIdx.x;
    const int wid  = tid >> 5;
    const int lane = tid & 31;
    const int wm = (wid >> 2) * 64;     // 0 / 64
    const int wn = (wid & 3) * 32;      // 0/32/64/96

    // global-load mapping: 2 threads per row; each covers 16 floats (4x float4)
    const int glr = tid >> 1;           // 0..127 (row)
    const int glf = (tid & 1) * 16;     // float offset within 32-float chunk
    const int glu = (tid & 1) * 8;      // half2-unit offset (8 units = 16 halves)

    const int lr = lane >> 2;           // 0..7
    const int kq = lane & 3;            // 0..3 (half2 unit -> halves 2kq, 2kq+1)

    float acc[4][4][4];
    #pragma unroll
    for (int mi = 0; mi < 4; mi++)
        #pragma unroll
        for (int ni = 0; ni < 4; ni++)
            #pragma unroll
            for (int e = 0; e < 4; e++) acc[mi][ni][e] = 0.f;

    float4 pa[4], pw[4];                // prefetch registers (16 floats each matrix)

    // prologue: load chunk 0
    #pragma unroll
    for (int j = 0; j < 4; j++) {
        pa[j] = *(const float4*)&A[(size_t)(row0 + glr) * K + glf + j * 4];
        pw[j] = *(const float4*)&W[(size_t)(col0 + glr) * K + glf + j * 4];
    }
    {
        uint32_t ua[8], uw[8];
        #pragma unroll
        for (int j = 0; j < 4; j++) {
            ua[2*j]   = f2h2(pa[j].x, pa[j].y);
            ua[2*j+1] = f2h2(pa[j].z, pa[j].w);
            uw[2*j]   = f2h2(pw[j].x, pw[j].y);
            uw[2*j+1] = f2h2(pw[j].z, pw[j].w);
        }
        uint32_t* dst = &As[0][glr * SMS2 + glu];
        *(uint4*)dst       = *(uint4*)&ua[0];
        *(uint4*)(dst + 4) = *(uint4*)&ua[4];
        uint32_t* dsw = &Ws[0][glr * SMS2 + glu];
        *(uint4*)dsw       = *(uint4*)&uw[0];
        *(uint4*)(dsw + 4) = *(uint4*)&uw[4];
    }
    __syncthreads();

    int p = 0;
    for (int k0 = 0; k0 < K; k0 += 32) {
        const bool has_next = (k0 + 32 < K);
        if (has_next) {
            #pragma unroll
            for (int j = 0; j < 4; j++) {
                pa[j] = *(const float4*)&A[(size_t)(row0 + glr) * K + k0 + 32 + glf + j * 4];
                pw[j] = *(const float4*)&W[(size_t)(col0 + glr) * K + k0 + 32 + glf + j * 4];
            }
        }

        // compute current buffer: 2 k16-steps x 16 MMAs
        #pragma unroll
        for (int ks = 0; ks < 2; ks++) {
            const int ksu = ks * 8;     // half2-unit base (8 units = 16 halves)
            uint32_t a[4][4], b[4][2];
            #pragma unroll
            for (int mi = 0; mi < 4; mi++) {
                const int r = wm + mi * 16 + lr;
                a[mi][0] = As[p][r * SMS2 + ksu + kq];
                a[mi][1] = As[p][(r + 8) * SMS2 + ksu + kq];
                a[mi][2] = As[p][r * SMS2 + ksu + kq + 4];
                a[mi][3] = As[p][(r + 8) * SMS2 + ksu + kq + 4];
            }
            #pragma unroll
            for (int ni = 0; ni < 4; ni++) {
                const int c = wn + ni * 8 + lr;
                b[ni][0] = Ws[p][c * SMS2 + ksu + kq];
                b[ni][1] = Ws[p][c * SMS2 + ksu + kq + 4];
            }
            #pragma unroll
            for (int mi = 0; mi < 4; mi++)
                #pragma unroll
                for (int ni = 0; ni < 4; ni++)
                    mma_f16(acc[mi][ni], a[mi], b[ni]);
        }

        if (has_next) {
            uint32_t ua[8], uw[8];
            #pragma unroll
            for (int j = 0; j < 4; j++) {
                ua[2*j]   = f2h2(pa[j].x, pa[j].y);
                ua[2*j+1] = f2h2(pa[j].z, pa[j].w);
                uw[2*j]   = f2h2(pw[j].x, pw[j].y);
                uw[2*j+1] = f2h2(pw[j].z, pw[j].w);
            }
            uint32_t* dst = &As[p ^ 1][glr * SMS2 + glu];
            *(uint4*)dst       = *(uint4*)&ua[0];
            *(uint4*)(dst + 4) = *(uint4*)&ua[4];
            uint32_t* dsw = &Ws[p ^ 1][glr * SMS2 + glu];
            *(uint4*)dsw       = *(uint4*)&uw[0];
            *(uint4*)(dsw + 4) = *(uint4*)&uw[4];
            __syncthreads();
            p ^= 1;
        }
    }

    // epilogue: c0 (r0,c), c1 (r0,c+1), c2 (r1,c), c3 (r1,c+1)
    const int crow = lane >> 2;
    const int ccol = (lane & 3) * 2;
    #pragma unroll
    for (int mi = 0; mi < 4; mi++) {
        const int r0 = row0 + wm + mi * 16 + crow;
        #pragma unroll
        for (int ni = 0; ni < 4; ni++) {
            const int c = col0 + wn + ni * 8 + ccol;
            const float b0 = bias[c], b1 = bias[c + 1];
            float2 v0, v1;
            v0.x = acc[mi][ni][0] + b0; v0.y = acc[mi][ni][1] + b1;
            v1.x = acc[mi][ni][2] + b0; v1.y = acc[mi][ni][3] + b1;
            if (RELU) {
                v0.x = fmaxf(v0.x, 0.f); v0.y = fmaxf(v0.y, 0.f);
                v1.x = fmaxf(v1.x, 0.f); v1.y = fmaxf(v1.y, 0.f);
            }
            *(float2*)&C[(size_t)r0 * Ncols + c] = v0;
            *(float2*)&C[(size_t)(r0 + 8) * Ncols + c] = v1;
        }
    }
}

// ---------------- phi GEMM: xp[bh][n][m] = NORM * sum_d Act[b,n,h*64+d]*proj[m][d] ----------------
// grid = (M/64=4, N/64=64, BH=64), block = 256
__global__ void phi_gemm_kernel(const float* __restrict__ Act,
                                const float* __restrict__ proj,
                                float* __restrict__ Xp) {
    const int z = blockIdx.z;            // bh
    const int b = z >> 4, h = z & 15;
    const float* A = Act + (size_t)b * N_ * D_ + h * DH_;   // rows stride D_
    float* C = Xp + (size_t)z * N_ * M_;

    __shared__ float As[16][65];
    __shared__ float Ws[16][65];
    const int row0 = blockIdx.y * 64;
    const int col0 = blockIdx.x * 64;
    const int tid = threadIdx.x;
    const int lk = tid & 15, lm = tid >> 4;
    const int tx = tid & 15, ty = tid >> 4;
    float acc[4][4];
    #pragma unroll
    for (int i = 0; i < 4; i++)
        #pragma unroll
        for (int j = 0; j < 4; j++) acc[i][j] = 0.f;

    for (int k0 = 0; k0 < DH_; k0 += 16) {
        #pragma unroll
        for (int i = 0; i < 4; i++) {
            int m = lm + i * 16;
            As[lk][m] = A[(size_t)(row0 + m) * D_ + k0 + lk];
            Ws[lk][m] = proj[(size_t)(col0 + m) * DH_ + k0 + lk];
        }
        __syncthreads();
        #pragma unroll
        for (int k = 0; k < 16; k++) {
            float a[4], bb[4];
            #pragma unroll
            for (int i = 0; i < 4; i++) a[i] = As[k][ty * 4 + i];
            #pragma unroll
            for (int j = 0; j < 4; j++) bb[j] = Ws[k][tx * 4 + j];
            #pragma unroll
            for (int i = 0; i < 4; i++)
                #pragma unroll
                for (int j = 0; j < 4; j++)
                    acc[i][j] += a[i] * bb[j];
        }
        __syncthreads();
    }
    #pragma unroll
    for (int i = 0; i < 4; i++) {
        int r = row0 + ty * 4 + i;
        #pragma unroll
        for (int j = 0; j < 4; j++)
            C[(size_t)r * M_ + col0 + tx * 4 + j] = acc[i][j] * NORM_;
    }
}

// ---------------- per-(b,h) global max over raw xp ----------------
__global__ void bhmax_kernel(const float* __restrict__ Xp, float* __restrict__ outMax) {
    const int bh = blockIdx.x;
    const float4* p = (const float4*)(Xp + (size_t)bh * N_ * M_);
    const int tot = N_ * M_ / 4;
    float m = -3.4e38f;
    for (int i = threadIdx.x; i < tot; i += 256) {
        float4 v = p[i];
        m = fmaxf(m, fmaxf(fmaxf(v.x, v.y), fmaxf(v.z, v.w)));
    }
    __shared__ float red[256];
    red[threadIdx.x] = m;
    __syncthreads();
    for (int o = 128; o >= 1; o >>= 1) {
        if (threadIdx.x < o) red[threadIdx.x] = fmaxf(red[threadIdx.x], red[threadIdx.x + o]);
        __syncthreads();
    }
    if (threadIdx.x == 0) outMax[bh] = red[0];
}

// ---------------- finalize: xp -> RATIO*(exp(xp - diag - stab)+eps) ----------------
// grid = BH_*N_ blocks, block = 256 (one thread per m)
template<bool ISQ>
__global__ void phi_finalize_kernel(float* __restrict__ Xp,
                                    const float* __restrict__ Act,
                                    const float* __restrict__ bhmaxArr) {
    const int row = blockIdx.x;          // bh*N + n
    const int bh = row >> 12;
    const int n  = row & (N_ - 1);
    const int b = bh >> 4, h = bh & 15;
    const int t = threadIdx.x;
    __shared__ float red[256];

    const float* x = Act + ((size_t)b * N_ + n) * D_ + h * DH_;
    float ss = 0.f;
    if (t < 64) { float v = x[t]; ss = v * v; }
    red[t] = ss;
    __syncthreads();
    for (int o = 32; o >= 1; o >>= 1) {
        if (t < o) red[t] += red[t + o];
        __syncthreads();
    }
    const float diag = red[0] * DIAGF_;
    __syncthreads();

    float xp = Xp[(size_t)row * M_ + t];
    float stab;
    if (ISQ) {
        red[t] = xp;
        __syncthreads();
        for (int o = 128; o >= 1; o >>= 1) {
            if (t < o) red[t] = fmaxf(red[t], red[t + o]);
            __syncthreads();
        }
        stab = red[0];
    } else {
        stab = bhmaxArr[bh];
    }
    Xp[(size_t)row * M_ + t] = RATIO_ * (__expf(xp - diag - stab) + EPSK_);
}

// ---------------- k_sum[bh][m] = sum_n kp[bh][n][m] ----------------
__global__ void ksum_kernel(const float* __restrict__ Kp, float* __restrict__ ks) {
    const int bh = blockIdx.x;
    const float* p = Kp + (size_t)bh * N_ * M_ + threadIdx.x;
    float s = 0.f;
    #pragma unroll 8
    for (int n = 0; n < N_; n++) s += p[(size_t)n * M_];
    ks[bh * M_ + threadIdx.x] = s;
}

__global__ void zero_kernel(float* __restrict__ p, int n) {
    int i = blockIdx.x * 256 + threadIdx.x;
    if (i < n) p[i] = 0.f;
}

// ---------------- ctx[bh][m][d] = sum_n kp[bh][n][m] * v[b,n,h*64+d] ----------------
// grid = (8 splits, BH_), block = (64, 4). float atomics into zeroed ctx.
__global__ void ctx_kernel(const float* __restrict__ Kp,
                           const float* __restrict__ V,
                           float* __restrict__ ctx) {
    const int bh = blockIdx.y;
    const int b = bh >> 4, h = bh & 15;
    const int d = threadIdx.x;
    const int tg = threadIdx.y;          // 0..3 -> m block of 64
    const int n0 = blockIdx.x * (N_ / 8);

    float acc[64];
    #pragma unroll
    for (int i = 0; i < 64; i++) acc[i] = 0.f;

    const float* kp = Kp + (size_t)bh * N_ * M_ + tg * 64;
    const float* v  = V + (size_t)b * N_ * D_ + h * DH_ + d;

    for (int n = n0; n < n0 + N_ / 8; n++) {
        float vv = v[(size_t)n * D_];
        const float* kr = kp + (size_t)n * M_;
        #pragma unroll
        for (int i = 0; i < 64; i++) acc[i] += kr[i] * vv;
    }
    float* cb = ctx + (size_t)bh * M_ * DH_ + (tg * 64) * DH_ + d;
    #pragma unroll
    for (int i = 0; i < 64; i++) atomicAdd(cb + i * DH_, acc[i]);
}

// ---------------- out[b,n,h*64+d] = (sum_m qp*ctx[m][d]) / (sum_m qp*ksum[m]) ----------------
// grid = (N/8, BH_), block = (64, 8), dyn smem = (256*64 + 256) floats
__global__ void attn_out_kernel(const float* __restrict__ Qp,
                                const float* __restrict__ ctx,
                                const float* __restrict__ ksum,
                                float* __restrict__ out) {
    extern __shared__ float sh[];
    float* ctx_sh = sh;                 // [256*64]
    float* ks_sh  = sh + M_ * DH_;
    const int bh = blockIdx.y;
    const int b = bh >> 4, h = bh & 15;
    const int tid = threadIdx.y * 64 + threadIdx.x;

    for (int i = tid; i < M_ * DH_; i += 512)
        ctx_sh[i] = ctx[(size_t)bh * M_ * DH_ + i];
    if (tid < M_) ks_sh[tid] = ksum[bh * M_ + tid];
    __syncthreads();

    const int n = blockIdx.x * 8 + threadIdx.y;
    const int d = threadIdx.x;
    const float* qp = Qp + ((size_t)bh * N_ + n) * M_;
    float acc = 0.f, den = 0.f;
    #pragma unroll 8
    for (int m = 0; m < M_; m++) {
        float q = qp[m];
        acc += q * ctx_sh[m * 64 + d];
        den += q * ks_sh[m];
    }
    out[((size_t)b * N_ + n) * D_ + h * DH_ + d] = acc / den;
}

// ---------------- LN(X + Res) * g + b ----------------
// grid = RTOT_, block = 256 (4 cols/thread)
__global__ void ln_kernel(const float* __restrict__ X,
                          const float* __restrict__ Res,
                          const float* __restrict__ g,
                          const float* __restrict__ be,
                          float* __restrict__ out) {
    const int row = blockIdx.x;
    const float* x = X + (size_t)row * D_;
    const float* r = Res + (size_t)row * D_;
    const int t = threadIdx.x;
    float v[4]; float s = 0.f, ss = 0.f;
    #pragma unroll
    for (int i = 0; i < 4; i++) {
        int c = t + i * 256;
        v[i] = x[c] + r[c];
        s += v[i]; ss += v[i] * v[i];
    }
    __shared__ float rs[256], rss[256];
    rs[t] = s; rss[t] = ss;
    __syncthreads();
    for (int o = 128; o >= 1; o >>= 1) {
        if (t < o) { rs[t] += rs[t + o]; rss[t] += rss[t + o]; }
        __syncthreads();
    }
    const float mean = rs[0] * (1.f / D_);
    const float var = rss[0] * (1.f / D_) - mean * mean;
    const float inv = rsqrtf(var + LNEPS_);
    #pragma unroll
    for (int i = 0; i < 4; i++) {
        int c = t + i * 256;
        out[(size_t)row * D_ + c] = (v[i] - mean) * inv * g[c] + be[c];
    }
}

// ---------------- host launcher ----------------
extern "C" void kernel_launch(void* const* d_in, const int* in_sizes, int n_in,
                              void* d_out, int out_size) {
    const float* video = (const float*)d_in[0];
    const float* Wq = (const float*)d_in[1];
    const float* bq = (const float*)d_in[2];
    const float* Wk = (const float*)d_in[3];
    const float* bk = (const float*)d_in[4];
    const float* Wv = (const float*)d_in[5];
    const float* bv = (const float*)d_in[6];
    const float* Wo = (const float*)d_in[7];
    const float* bo = (const float*)d_in[8];
    const float* proj = (const float*)d_in[9];
    const float* W1 = (const float*)d_in[10];
    const float* b1 = (const float*)d_in[11];
    const float* W2 = (const float*)d_in[12];
    const float* b2 = (const float*)d_in[13];
    const float* g2 = (const float*)d_in[14];
    const float* be2 = (const float*)d_in[15];
    const float* g3 = (const float*)d_in[16];
    const float* be3 = (const float*)d_in[17];
    float* out = (float*)d_out;

    float *Q, *K, *V, *PQ, *PK, *CTX, *KS, *BHM, *HH;
    cudaGetSymbolAddress((void**)&Q,  g_Q);
    cudaGetSymbolAddress((void**)&K,  g_K);
    cudaGetSymbolAddress((void**)&V,  g_V);
    cudaGetSymbolAddress((void**)&PQ, g_phiQ);
    cudaGetSymbolAddress((void**)&PK, g_phiK);
    cudaGetSymbolAddress((void**)&CTX, g_ctx);
    cudaGetSymbolAddress((void**)&KS, g_ksum);
    cudaGetSymbolAddress((void**)&BHM, g_bhmax);
    cudaGetSymbolAddress((void**)&HH, g_H);

    // 1) QKV projections (fp16 tensor cores, pipelined)
    dim3 gQKV(D_ / 128, RTOT_ / 128);
    tgemm_bias_kernel<false><<<gQKV, 256>>>(video, Wq, bq, Q, D_, D_);
    tgemm_bias_kernel<false><<<gQKV, 256>>>(video, Wk, bk, K, D_, D_);
    tgemm_bias_kernel<false><<<gQKV, 256>>>(video, Wv, bv, V, D_, D_);

    // 2) phi projections (raw xp) — fp32 for exp-path precision
    dim3 gPhi(M_ / 64, N_ / 64, BH_);
    phi_gemm_kernel<<<gPhi, 256>>>(Q, proj, PQ);
    phi_gemm_kernel<<<gPhi, 256>>>(K, proj, PK);

    // 3) key stabilizer: per-(b,h) max over raw xp_k
    bhmax_kernel<<<BH_, 256>>>(PK, BHM);

    // 4) exp finalize
    phi_finalize_kernel<true ><<<BH_ * N_, 256>>>(PQ, Q, nullptr);
    phi_finalize_kernel<false><<<BH_ * N_, 256>>>(PK, K, BHM);

    // 5) k_sum
    ksum_kernel<<<BH_, 256>>>(PK, KS);

    // 6) ctx = kp^T @ v  (zero + atomic partials over 8 n-splits)
    zero_kernel<<<(BH_ * M_ * DH_ + 255) / 256, 256>>>(CTX, BH_ * M_ * DH_);
    ctx_kernel<<<dim3(8, BH_), dim3(64, 4)>>>(PK, V, CTX);

    // 7) out = (qp @ ctx) / (qp @ k_sum), written in [b,n,h*dh] layout (reuse Q)
    const int smem = (M_ * DH_ + M_) * sizeof(float);
    cudaFuncSetAttribute(attn_out_kernel, cudaFuncAttributeMaxDynamicSharedMemorySize, smem);
    attn_out_kernel<<<dim3(N_ / 8, BH_), dim3(64, 8), smem>>>(PQ, CTX, KS, Q);

    // 8) output projection (reuse K as attn buffer)
    tgemm_bias_kernel<false><<<gQKV, 256>>>(Q, Wo, bo, K, D_, D_);

    // 9) x = LN(video + attn) (reuse V)
    ln_kernel<<<RTOT_, 256>>>(K, video, g2, be2, V);

    // 10) ffn hidden = relu(x @ W1^T + b1)
    tgemm_bias_kernel<true><<<dim3(DFF_ / 128, RTOT_ / 128), 256>>>(V, W1, b1, HH, D_, DFF_);

    // 11) ffn out = hidden @ W2^T + b2 (reuse Q)
    tgemm_bias_kernel<false><<<dim3(D_ / 128, RTOT_ / 128), 256>>>(HH, W2, b2, Q, DFF_, D_);

    // 12) final LN -> d_out
    ln_kernel<<<RTOT_, 256>>>(Q, V, g3, be3, out);
}